// round 15
// baseline (speedup 1.0000x reference)
#include <cuda_runtime.h>

#define B_    16
#define C_    64
#define WH    65536                 // 256*256
#define NELEM (B_ * C_ * WH)        // 67,108,864 elements
#define EPS_  0.001f

#define NBLK_ST     1024            // one plane (256 KB) per block — single wave
#define EV_START    624             // planes [624,1024): evict_last (104 MB kept)
#define NBLK_NORM   4096            // 4096 float4 (16 KB) per block, 512 thr

// ---- scratch (device globals; plain stores, rewritten every launch) ----
__device__ float g_Sp[NBLK_ST];              // per-plane sum   [b*64+c]
__device__ float g_Qp[NBLK_ST];              // per-plane sumsq
__device__ int   g_cnt[B_];                  // per-batch masked count
__device__ float g_inv[C_];                  // 1/sqrt(var+eps)
__device__ int   g_done;                     // last-block-done counter (self-reset)

__device__ __forceinline__ void acc_f32x2(unsigned long long& s,
                                          unsigned long long& q,
                                          unsigned long long v) {
    asm("add.rn.f32x2 %0, %0, %1;" : "+l"(s) : "l"(v));
    asm("fma.rn.f32x2 %0, %1, %1, %0;" : "+l"(q) : "l"(v));
}
__device__ __forceinline__ float2 unpack2(unsigned long long v) {
    float2 r;
    asm("mov.b64 {%0, %1}, %2;" : "=f"(r.x), "=f"(r.y) : "l"(v));
    return r;
}
// 32B load with L2 evict_last hint (sm_103 requires .v4.b64 width for this
// modifier). Lines are retained preferentially so the norm kernel (reverse
// order) can consume them from L2 instead of DRAM.
struct U4 { unsigned long long a, b, c, d; };
__device__ __forceinline__ U4 ldg_evl32(const void* p) {
    U4 r;
    asm("ld.global.nc.L2::evict_last.v4.u64 {%0, %1, %2, %3}, [%4];"
        : "=l"(r.a), "=l"(r.b), "=l"(r.c), "=l"(r.d) : "l"(p));
    return r;
}

// ---- stats: S_c = sum x, Q_c = sum x^2 over everything (unmasked pixels are
// exactly 0 in every channel => no mask needed for sums). One plane per block,
// 1024 blocks = ONE wave. The 16 channel-0 blocks also count their own
// nonzeros (keep=0 => x[b,0,p]==0 exactly). Planes >= EV_START are read with
// L2::evict_last so their 104 MB survive into the norm kernel's L2 window.
// Last finishing block runs the finalize inline (partials L2-hot). ----
__global__ void __launch_bounds__(256) k_stats(const float* __restrict__ x) {
    const int tid = threadIdx.x;
    const int plane = blockIdx.x;                // b*64 + c
    bool docnt = ((plane & (C_ - 1)) == 0);
    __shared__ float ss[8], sq[8];
    __shared__ int   scn[8];
    __shared__ int   sh_last;
    __shared__ int   sh_n[B_];
    __shared__ int   sh_nmax;

    const float* pbase = x + (size_t)plane * WH;
    unsigned long long sA = 0, sB = 0, qA = 0, qB = 0;
    int cnt = 0;
    if (!docnt) {
        if (plane >= EV_START) {
            // 32 B per thread per iter: 256 thr * 32 B * 32 iters = 256 KB
            #pragma unroll 4
            for (int k = 0; k < 32; k++) {
                U4 v = ldg_evl32(pbase + (k * 256 + tid) * 8);
                acc_f32x2(sA, qA, v.a);
                acc_f32x2(sB, qB, v.b);
                acc_f32x2(sA, qA, v.c);
                acc_f32x2(sB, qB, v.d);
            }
        } else {
            const ulonglong2* base = (const ulonglong2*)pbase;
            #pragma unroll 8
            for (int k = 0; k < 64; k++) {
                ulonglong2 v = __ldg(base + k * 256 + tid);
                acc_f32x2(sA, qA, v.x);
                acc_f32x2(sB, qB, v.y);
            }
        }
    } else {                                     // 16 / 1024 blocks: also count
        const float4* fbase = (const float4*)pbase;
        #pragma unroll 8
        for (int k = 0; k < 64; k++) {
            float4 v = __ldg(fbase + k * 256 + tid);
            unsigned long long p0, p1;
            asm("mov.b64 %0, {%1, %2};" : "=l"(p0) : "f"(v.x), "f"(v.y));
            asm("mov.b64 %0, {%1, %2};" : "=l"(p1) : "f"(v.z), "f"(v.w));
            acc_f32x2(sA, qA, p0);
            acc_f32x2(sB, qB, p1);
            cnt += (int)(v.x != 0.0f) + (int)(v.y != 0.0f)
                 + (int)(v.z != 0.0f) + (int)(v.w != 0.0f);
        }
        cnt = __reduce_add_sync(0xFFFFFFFFu, cnt);
    }
    float2 a = unpack2(sA), b2 = unpack2(sB);
    float2 c2 = unpack2(qA), d2 = unpack2(qB);
    float s = (a.x + a.y) + (b2.x + b2.y);
    float q = (c2.x + c2.y) + (d2.x + d2.y);
    #pragma unroll
    for (int o = 16; o; o >>= 1) {
        s += __shfl_xor_sync(0xFFFFFFFFu, s, o);
        q += __shfl_xor_sync(0xFFFFFFFFu, q, o);
    }
    int w = tid >> 5;
    if ((tid & 31) == 0) { ss[w] = s; sq[w] = q; scn[w] = cnt; }
    __syncthreads();
    if (tid == 0) {
        float S = 0.0f, Q = 0.0f;
        #pragma unroll
        for (int i = 0; i < 8; i++) { S += ss[i]; Q += sq[i]; }
        g_Sp[plane] = S;
        g_Qp[plane] = Q;
        if (docnt) {
            int t = 0;
            #pragma unroll
            for (int i = 0; i < 8; i++) t += scn[i];
            g_cnt[plane >> 6] = t;
        }
        __threadfence();                         // release partials
        int old = atomicAdd(&g_done, 1);
        sh_last = (old == NBLK_ST - 1) ? 1 : 0;
        if (sh_last) g_done = 0;                 // reset for next graph replay
    }
    __syncthreads();
    if (!sh_last) return;

    // ---- inline finalize, exactly one block, partials L2-hot ----
    __threadfence();                             // acquire
    if (tid < B_) sh_n[tid] = g_cnt[tid];
    __syncthreads();
    if (tid == 0) {
        int nmax = 0;
        #pragma unroll
        for (int b = 0; b < B_; b++) nmax = max(nmax, sh_n[b]);
        sh_nmax = nmax;
    }
    __syncthreads();
    int nmax = sh_nmax;
    int c = tid >> 2, j = tid & 3;               // 4 threads per channel
    float S = 0.0f, Q = 0.0f;
    #pragma unroll
    for (int b4 = 0; b4 < 4; b4++) {             // this thread: batches j*4+b4
        int b = j * 4 + b4;
        int pl = b * C_ + c;
        float Sp  = g_Sp[pl];
        float Qp  = g_Qp[pl];
        float x00 = __ldg(&x[(size_t)pl << 16]);
        float pad = (float)(nmax - sh_n[b]);
        S += fmaf(pad, x00, Sp);
        Q += fmaf(pad * x00, x00, Qp);
    }
    S += __shfl_xor_sync(0xFFFFFFFFu, S, 1, 4);
    S += __shfl_xor_sync(0xFFFFFFFFu, S, 2, 4);
    Q += __shfl_xor_sync(0xFFFFFFFFu, Q, 1, 4);
    Q += __shfl_xor_sync(0xFFFFFFFFu, Q, 2, 4);
    if (j == 0) {
        float total = (float)(B_ * nmax);
        float mean  = S / total;
        float var   = Q / total - mean * mean;
        g_inv[c] = rsqrtf(var + EPS_);
    }
}

// ---- normalize: out = x * inv[c] unconditionally (unmasked x are exact 0;
// (0,0) pad override is also x00*inv). 16 KB per block (512 thr x 8 float4),
// all loads front-batched. REVERSE address order: the evict_last planes
// (highest addresses) are consumed first, straight from L2. ----
__global__ void __launch_bounds__(512) k_norm(const float* __restrict__ x,
                                              float* __restrict__ out) {
    const int tid = threadIdx.x;
    int blk = (NBLK_NORM - 1) - blockIdx.x;
    size_t base4 = (size_t)blk * 4096;               // float4 index of block base
    int c = (int)(base4 >> 14) & (C_ - 1);           // block lies in one plane
    float inv = __ldg(&g_inv[c]);
    float4 v[8];
    #pragma unroll
    for (int k = 0; k < 8; k++)                      // 8 reads in flight
        v[k] = __ldcs((const float4*)x + base4 + k * 512 + tid);
    #pragma unroll
    for (int k = 0; k < 8; k++) {
        float4 o;
        o.x = v[k].x * inv; o.y = v[k].y * inv;
        o.z = v[k].z * inv; o.w = v[k].w * inv;
        __stcs((float4*)out + base4 + k * 512 + tid, o);
    }
}

extern "C" void kernel_launch(void* const* d_in, const int* in_sizes, int n_in,
                              void* d_out, int out_size) {
    const float* x = (const float*)d_in[0];
    float* out = (float*)d_out;
    k_stats<<<NBLK_ST, 256>>>(x);
    k_norm <<<NBLK_NORM, 512>>>(x, out);
}

// round 16
// speedup vs baseline: 1.0041x; 1.0041x over previous
#include <cuda_runtime.h>

#define B_    16
#define C_    64
#define WH    65536                 // 256*256
#define NELEM (B_ * C_ * WH)        // 67,108,864 elements
#define EPS_  0.001f

#define NBLK_ST     1024            // one plane (256 KB) per block
#define NBLK_NORM   4096            // 4096 float4 (16 KB) per block, 512 thr

// ---- scratch (device globals; plain stores, rewritten every launch) ----
__device__ float g_Sp[NBLK_ST];              // per-plane sum   [b*64+c]
__device__ float g_Qp[NBLK_ST];              // per-plane sumsq
__device__ int   g_cnt[B_];                  // per-batch masked count
__device__ float g_inv[C_];                  // 1/sqrt(var+eps)
__device__ int   g_done;                     // last-block-done counter (self-reset)

__device__ __forceinline__ void acc_f32x2(unsigned long long& s,
                                          unsigned long long& q,
                                          unsigned long long v) {
    asm("add.rn.f32x2 %0, %0, %1;" : "+l"(s) : "l"(v));
    asm("fma.rn.f32x2 %0, %1, %1, %0;" : "+l"(q) : "l"(v));
}
__device__ __forceinline__ float2 unpack2(unsigned long long v) {
    float2 r;
    asm("mov.b64 {%0, %1}, %2;" : "=f"(r.x), "=f"(r.y) : "l"(v));
    return r;
}

// ---- stats: S_c = sum x, Q_c = sum x^2 over everything (unmasked pixels are
// exactly 0 in every channel => no mask needed for sums). One plane per block.
// __launch_bounds__(256, 8) caps regs at 32 => 8 CTAs/SM => 1184 resident
// slots >= 1024 blocks: a TRUE single wave, no quantization tail. The 16
// channel-0 blocks also count their own nonzeros (keep=0 => x[b,0,p]==0
// exactly). Last finishing block runs the finalize inline (partials L2-hot). ----
__global__ void __launch_bounds__(256, 8) k_stats(const float* __restrict__ x) {
    const int tid = threadIdx.x;
    const int plane = blockIdx.x;                // b*64 + c
    bool docnt = ((plane & (C_ - 1)) == 0);
    __shared__ float ss[8], sq[8];
    __shared__ int   scn[8];
    __shared__ int   sh_last;
    __shared__ int   sh_n[B_];
    __shared__ int   sh_nmax;

    const ulonglong2* base = (const ulonglong2*)(x + (size_t)plane * WH);
    unsigned long long sA = 0, sB = 0, qA = 0, qB = 0;
    int cnt = 0;
    if (!docnt) {
        #pragma unroll 8
        for (int k = 0; k < 64; k++) {
            ulonglong2 v = __ldg(base + k * 256 + tid);
            acc_f32x2(sA, qA, v.x);
            acc_f32x2(sB, qB, v.y);
        }
    } else {                                     // 16 / 1024 blocks: also count
        const float4* fbase = (const float4*)base;
        #pragma unroll 8
        for (int k = 0; k < 64; k++) {
            float4 v = __ldg(fbase + k * 256 + tid);
            unsigned long long p0, p1;
            asm("mov.b64 %0, {%1, %2};" : "=l"(p0) : "f"(v.x), "f"(v.y));
            asm("mov.b64 %0, {%1, %2};" : "=l"(p1) : "f"(v.z), "f"(v.w));
            acc_f32x2(sA, qA, p0);
            acc_f32x2(sB, qB, p1);
            cnt += (int)(v.x != 0.0f) + (int)(v.y != 0.0f)
                 + (int)(v.z != 0.0f) + (int)(v.w != 0.0f);
        }
        cnt = __reduce_add_sync(0xFFFFFFFFu, cnt);
    }
    float2 a = unpack2(sA), b2 = unpack2(sB);
    float2 c2 = unpack2(qA), d2 = unpack2(qB);
    float s = (a.x + a.y) + (b2.x + b2.y);
    float q = (c2.x + c2.y) + (d2.x + d2.y);
    #pragma unroll
    for (int o = 16; o; o >>= 1) {
        s += __shfl_xor_sync(0xFFFFFFFFu, s, o);
        q += __shfl_xor_sync(0xFFFFFFFFu, q, o);
    }
    int w = tid >> 5;
    if ((tid & 31) == 0) { ss[w] = s; sq[w] = q; scn[w] = cnt; }
    __syncthreads();
    if (tid == 0) {
        float S = 0.0f, Q = 0.0f;
        #pragma unroll
        for (int i = 0; i < 8; i++) { S += ss[i]; Q += sq[i]; }
        g_Sp[plane] = S;
        g_Qp[plane] = Q;
        if (docnt) {
            int t = 0;
            #pragma unroll
            for (int i = 0; i < 8; i++) t += scn[i];
            g_cnt[plane >> 6] = t;
        }
        __threadfence();                         // release partials
        int old = atomicAdd(&g_done, 1);
        sh_last = (old == NBLK_ST - 1) ? 1 : 0;
        if (sh_last) g_done = 0;                 // reset for next graph replay
    }
    __syncthreads();
    if (!sh_last) return;

    // ---- inline finalize, exactly one block, partials L2-hot ----
    __threadfence();                             // acquire
    if (tid < B_) sh_n[tid] = g_cnt[tid];
    __syncthreads();
    if (tid == 0) {
        int nmax = 0;
        #pragma unroll
        for (int b = 0; b < B_; b++) nmax = max(nmax, sh_n[b]);
        sh_nmax = nmax;
    }
    __syncthreads();
    int nmax = sh_nmax;
    int c = tid >> 2, j = tid & 3;               // 4 threads per channel
    float S = 0.0f, Q = 0.0f;
    #pragma unroll
    for (int b4 = 0; b4 < 4; b4++) {             // this thread: batches j*4+b4
        int b = j * 4 + b4;
        int pl = b * C_ + c;
        float Sp  = g_Sp[pl];
        float Qp  = g_Qp[pl];
        float x00 = __ldg(&x[(size_t)pl << 16]);
        float pad = (float)(nmax - sh_n[b]);
        S += fmaf(pad, x00, Sp);
        Q += fmaf(pad * x00, x00, Qp);
    }
    S += __shfl_xor_sync(0xFFFFFFFFu, S, 1, 4);
    S += __shfl_xor_sync(0xFFFFFFFFu, S, 2, 4);
    Q += __shfl_xor_sync(0xFFFFFFFFu, Q, 1, 4);
    Q += __shfl_xor_sync(0xFFFFFFFFu, Q, 2, 4);
    if (j == 0) {
        float total = (float)(B_ * nmax);
        float mean  = S / total;
        float var   = Q / total - mean * mean;
        g_inv[c] = rsqrtf(var + EPS_);
    }
}

// ---- normalize: out = x * inv[c] unconditionally (unmasked x are exact 0;
// (0,0) pad override is also x00*inv). 16 KB per block (512 thr x 8 float4),
// all loads front-batched: long read burst then long write burst. Reverse
// address order to catch the L2 tail left by stats. ----
__global__ void __launch_bounds__(512) k_norm(const float* __restrict__ x,
                                              float* __restrict__ out) {
    const int tid = threadIdx.x;
    int blk = (NBLK_NORM - 1) - blockIdx.x;
    size_t base4 = (size_t)blk * 4096;               // float4 index of block base
    int c = (int)(base4 >> 14) & (C_ - 1);           // block lies in one plane
    float inv = __ldg(&g_inv[c]);
    float4 v[8];
    #pragma unroll
    for (int k = 0; k < 8; k++)                      // 8 reads in flight
        v[k] = __ldcs((const float4*)x + base4 + k * 512 + tid);
    #pragma unroll
    for (int k = 0; k < 8; k++) {
        float4 o;
        o.x = v[k].x * inv; o.y = v[k].y * inv;
        o.z = v[k].z * inv; o.w = v[k].w * inv;
        __stcs((float4*)out + base4 + k * 512 + tid, o);
    }
}

extern "C" void kernel_launch(void* const* d_in, const int* in_sizes, int n_in,
                              void* d_out, int out_size) {
    const float* x = (const float*)d_in[0];
    float* out = (float*)d_out;
    k_stats<<<NBLK_ST, 256>>>(x);
    k_norm <<<NBLK_NORM, 512>>>(x, out);
}